// round 14
// baseline (speedup 1.0000x reference)
#include <cuda_runtime.h>
#include <cuda_fp16.h>
#include <math.h>
#include <stdint.h>

#define N_NODES   100000
#define N_EDGES   1600000
#define N_GRAPHS  128
#define HID       128
#define N_CLASSES 10
#define NBLK      391            // ceil(N_NODES/256)
#define BM        64             // nodes per layer block (MMA M)
#define LGRID     ((N_NODES + BM - 1) / BM)   // 1563
#define THREADS   256
#define NSPLIT    16             // pool node-range splits per graph
#define KC        32             // W k-chunk size

// A tile rows: 128 fp16 + 8 pad = 272 B (stride 68 words -> conflict-free LDSM)
#define PADA      272
// W chunk rows: 32 fp16 + 8 pad = 80 B (stride 20 words -> conflict-free LDSM)
#define PADW      80
// dynamic smem layout (bytes)
#define SM_AH     0                      // A_hi: 64 x 272 = 17408
#define SM_AL     17408                  // A_lo: 17408
#define SM_WH     34816                  // W_hi chunk: 128 x 80 = 10240
#define SM_WL     45056                  // W_lo chunk: 10240
#define SM_CD     55296                  // cdm[64]
#define SM_CS     55552                  // csm[64]
#define SMEM_TOT  55808

// ---------------- scratch (static __device__, no runtime alloc) ----------------
__device__ float  g_deg_out[2][N_NODES];
__device__ float  g_deg_in [2][N_NODES];
__device__ float  g_cs     [2][N_NODES];
__device__ float  g_cd     [2][N_NODES];
__device__ float  g_h1     [2][N_NODES];
__device__ float  g_agg1   [2][N_NODES];       // layer-1 scalar aggregation (fused into fill)
__device__ float2 g_x1cs   [2][N_NODES];       // {agg1*cd, cs}
__device__ int    g_rowtmp [2][N_NODES];
__device__ int    g_bsum   [2][512];
__device__ int    g_boff   [2][512];
__device__ int    g_row    [2][N_NODES + 1];
__device__ int    g_cursor [2][N_NODES];
__device__ int    g_csr    [2][N_EDGES];
__device__ __align__(16) unsigned short g_hfA[2][N_NODES * HID];  // fp16 features
__device__ __align__(16) unsigned short g_hfB[2][N_NODES * HID];
__device__ float  g_hsO    [2][N_NODES * HID];  // layer-4 fp32 output (pool input)
__device__ __align__(16) unsigned short g_WtH[3][HID * HID];  // W^T fp16 hi
__device__ __align__(16) unsigned short g_WtL[3][HID * HID];  // W^T fp16 lo (residual)

// ---------------- helpers ----------------
__device__ __forceinline__ uint32_t smem_u32(const void* p) {
    uint32_t a;
    asm("{ .reg .u64 t; cvta.to.shared.u64 t, %1; cvt.u32.u64 %0, t; }" : "=r"(a) : "l"(p));
    return a;
}
__device__ __forceinline__ uint32_t packhf(float l, float h) {
    __half2 v = __floats2half2_rn(l, h);
    return *(uint32_t*)&v;
}
__device__ __forceinline__ float h_lo(uint32_t w) { __half2 v = *(__half2*)&w; return __low2float(v); }
__device__ __forceinline__ float h_hi(uint32_t w) { __half2 v = *(__half2*)&w; return __high2float(v); }

#define LDSM4(r0, r1, r2, r3, addr) \
    asm volatile("ldmatrix.sync.aligned.m8n8.x4.shared.b16 {%0,%1,%2,%3}, [%4];" \
        : "=r"(r0), "=r"(r1), "=r"(r2), "=r"(r3) : "r"(addr))

#define MMA16816(d, a0, a1, a2, a3, b0, b1) \
    asm volatile("mma.sync.aligned.m16n8k16.row.col.f32.f16.f16.f32 " \
        "{%0,%1,%2,%3}, {%4,%5,%6,%7}, {%8,%9}, {%0,%1,%2,%3};" \
        : "+f"((d)[0]), "+f"((d)[1]), "+f"((d)[2]), "+f"((d)[3]) \
        : "r"(a0), "r"(a1), "r"(a2), "r"(a3), "r"(b0), "r"(b1))

__device__ __forceinline__ void splithf(float v, __half& hi, __half& lo) {
    hi = __float2half_rn(v);
    lo = __float2half_rn(v - __half2float(hi));
}

// ---------------- prolog: fused zero + output-zero + W prep ----------------
// grid (NBLK, 2) x 256. Covers: per-branch array zeroing, d_out zeroing,
// and split-fp16 W transpose (3 x 16384 elements).
__global__ void k_init(float* __restrict__ out,
                       const float* __restrict__ W2, const float* __restrict__ W3,
                       const float* __restrict__ W4) {
    int br = blockIdx.y;
    int i = blockIdx.x * blockDim.x + threadIdx.x;
    if (i < N_NODES) {
        g_deg_out[br][i] = 0.f;
        g_deg_in [br][i] = 0.f;
        g_agg1   [br][i] = 0.f;
    }
    int gid = br * (NBLK * 256) + i;     // 0 .. 200191 unique
    if (gid < 2 * N_GRAPHS * HID) {
        out[gid] = 0.f;                   // 32768 elements
    } else if (gid < 2 * N_GRAPHS * HID + 3 * HID * HID) {
        int idx2 = gid - 2 * N_GRAPHS * HID;
        int which = idx2 / (HID * HID);
        int idx = idx2 - which * (HID * HID);
        const float* W = (which == 0) ? W2 : (which == 1) ? W3 : W4;
        int n = idx >> 7, k = idx & 127;
        __half hh, hl;
        splithf(W[k * HID + n], hh, hl);
        g_WtH[which][idx] = *(unsigned short*)&hh;
        g_WtL[which][idx] = *(unsigned short*)&hl;
    }
}

__global__ void k_degree(const int* __restrict__ s1, const int* __restrict__ d1,
                         const int* __restrict__ s2, const int* __restrict__ d2) {
    int br = blockIdx.y;
    const int* src = br ? s2 : s1;
    const int* dst = br ? d2 : d1;
    int e = blockIdx.x * blockDim.x + threadIdx.x;
    if (e < N_EDGES) {
        atomicAdd(&g_deg_out[br][src[e]], 1.0f);
        atomicAdd(&g_deg_in [br][dst[e]], 1.0f);
    }
}

__global__ void k_scan1() {
    __shared__ int sh[256];
    int br = blockIdx.y;
    int t = threadIdx.x, b = blockIdx.x;
    int i = b * 256 + t;
    int v = 0;
    if (i < N_NODES) {
        float od = g_deg_out[br][i], id = g_deg_in[br][i];
        float cs = rsqrtf(fmaxf(od, 1.0f));
        float cd = rsqrtf(fmaxf(id, 1.0f));
        g_cs[br][i] = cs; g_cd[br][i] = cd;
        g_h1[br][i] = id * cs;
        v = __float2int_rn(id);
    }
    sh[t] = v;
    __syncthreads();
    #pragma unroll
    for (int off = 1; off < 256; off <<= 1) {
        int add = (t >= off) ? sh[t - off] : 0;
        __syncthreads();
        sh[t] += add;
        __syncthreads();
    }
    if (i < N_NODES) g_rowtmp[br][i] = sh[t] - v;
    if (t == 255) g_bsum[br][b] = sh[255];
}

__global__ void k_scan2() {
    __shared__ int sh[512];
    int br = blockIdx.y;
    int t = threadIdx.x;
    int v = (t < NBLK) ? g_bsum[br][t] : 0;
    sh[t] = v;
    __syncthreads();
    #pragma unroll
    for (int off = 1; off < 512; off <<= 1) {
        int add = (t >= off) ? sh[t - off] : 0;
        __syncthreads();
        sh[t] += add;
        __syncthreads();
    }
    g_boff[br][t] = sh[t] - v;
}

__global__ void k_scan3() {
    int br = blockIdx.y;
    int i = blockIdx.x * blockDim.x + threadIdx.x;
    if (i < N_NODES) {
        int r = g_rowtmp[br][i] + g_boff[br][i >> 8];
        g_row[br][i] = r;
        g_cursor[br][i] = r;
    }
    if (i == 0) g_row[br][N_NODES] = N_EDGES;
}

// CSR fill + fused layer-1 scalar aggregation
__global__ void k_fill(const int* __restrict__ s1, const int* __restrict__ d1,
                       const int* __restrict__ s2, const int* __restrict__ d2) {
    int br = blockIdx.y;
    const int* src = br ? s2 : s1;
    const int* dst = br ? d2 : d1;
    int e = blockIdx.x * blockDim.x + threadIdx.x;
    if (e < N_EDGES) {
        int s = src[e], d = dst[e];
        int pos = atomicAdd(&g_cursor[br][d], 1);
        g_csr[br][pos] = s;
        atomicAdd(&g_agg1[br][d], g_h1[br][s]);
    }
}

// finalize {x1 = agg1*cd, cs}
__global__ void k_x1() {
    int br = blockIdx.y;
    int n = blockIdx.x * blockDim.x + threadIdx.x;
    if (n < N_NODES)
        g_x1cs[br][n] = make_float2(g_agg1[br][n] * g_cd[br][n], g_cs[br][n]);
}

// ---------------- layer building blocks ----------------

// store split-A: node nl (0..63), k-group lane*4, fp32 values v0..v3
__device__ __forceinline__ void store_A(char* smem, int nl, int lane,
                                        float v0, float v1, float v2, float v3) {
    __half h0, l0, h1, l1, h2, l2, h3, l3;
    splithf(v0, h0, l0); splithf(v1, h1, l1);
    splithf(v2, h2, l2); splithf(v3, h3, l3);
    uint32_t off = (uint32_t)(nl * PADA + lane * 8);
    *(uint2*)(smem + SM_AH + off) = make_uint2(packhf(__half2float(h0), __half2float(h1)),
                                               packhf(__half2float(h2), __half2float(h3)));
    *(uint2*)(smem + SM_AL + off) = make_uint2(packhf(__half2float(l0), __half2float(l1)),
                                               packhf(__half2float(l2), __half2float(l3)));
}

// split-A x split-W 3-term HMMA GEMM with W chunk staging + epilogue.
// warp tile: m16 rows ((warp&3)*16) x n64 cols ((warp>>2)*64)
__device__ __forceinline__ void mma_gemm(char* smem, uint32_t smem_base, int l, int nbase,
                                         const float* __restrict__ bb,
                                         const float* csm, int applyCs,
                                         unsigned short* outh, float* outf, int t) {
    int warp = t >> 5, lane = t & 31;
    int mr = (warp & 3) * 16;
    int nb = (warp >> 2) * 64;

    float acc[8][4];
    #pragma unroll
    for (int j = 0; j < 8; j++)
        #pragma unroll
        for (int c = 0; c < 4; c++) acc[j][c] = 0.f;

    uint32_t aOff   = (uint32_t)((mr + (lane & 15)) * PADA + ((lane >> 4) << 4));
    uint32_t aHBase = smem_base + SM_AH + aOff;
    uint32_t aLBase = smem_base + SM_AL + aOff;
    uint32_t bRow   = (uint32_t)(nb + ((lane >> 4) << 3) + (lane & 7));
    uint32_t bCol   = (uint32_t)(((lane >> 3) & 1) << 4);

    const unsigned short* WH = g_WtH[l];
    const unsigned short* WL = g_WtL[l];

    #pragma unroll
    for (int kc = 0; kc < 4; kc++) {
        __syncthreads();
        // stage W chunk [128 n][32 k] hi+lo
        #pragma unroll
        for (int i = 0; i < 2; i++) {
            int idx = t + i * 256;          // 512 uint4 per tile
            int row = idx >> 2, c = idx & 3;
            *(uint4*)(smem + SM_WH + row * PADW + c * 16) =
                *(const uint4*)(WH + row * HID + kc * KC + c * 8);
            *(uint4*)(smem + SM_WL + row * PADW + c * 16) =
                *(const uint4*)(WL + row * HID + kc * KC + c * 8);
        }
        __syncthreads();
        #pragma unroll
        for (int kk = 0; kk < 2; kk++) {
            int kglob = kc * KC + kk * 16;
            uint32_t a0, a1, a2, a3, e0, e1, e2, e3;
            LDSM4(a0, a1, a2, a3, aHBase + kglob * 2);
            LDSM4(e0, e1, e2, e3, aLBase + kglob * 2);
            #pragma unroll
            for (int j2 = 0; j2 < 4; j2++) {
                uint32_t boff = (bRow + j2 * 16) * PADW + bCol + kk * 32;
                uint32_t b0, b1, b2, b3;
                LDSM4(b0, b1, b2, b3, smem_base + SM_WH + boff);
                MMA16816(acc[j2 * 2],     a0, a1, a2, a3, b0, b1);
                MMA16816(acc[j2 * 2 + 1], a0, a1, a2, a3, b2, b3);
                MMA16816(acc[j2 * 2],     e0, e1, e2, e3, b0, b1);
                MMA16816(acc[j2 * 2 + 1], e0, e1, e2, e3, b2, b3);
                uint32_t c0, c1, c2, c3;
                LDSM4(c0, c1, c2, c3, smem_base + SM_WL + boff);
                MMA16816(acc[j2 * 2],     a0, a1, a2, a3, c0, c1);
                MMA16816(acc[j2 * 2 + 1], a0, a1, a2, a3, c2, c3);
            }
        }
    }

    int lm = lane >> 2;
    int ln = (lane & 3) * 2;
    int r0l = mr + lm;
    int row0 = nbase + r0l, row1 = row0 + 8;
    float sc0 = applyCs ? csm[r0l]     : 1.0f;
    float sc1 = applyCs ? csm[r0l + 8] : 1.0f;
    bool ok0 = row0 < N_NODES, ok1 = row1 < N_NODES;

    #pragma unroll
    for (int j = 0; j < 8; j++) {
        int col = nb + j * 8 + ln;
        float2 bv = *(const float2*)&bb[col];
        float o00 = fmaxf(acc[j][0] + bv.x, 0.f) * sc0;
        float o01 = fmaxf(acc[j][1] + bv.y, 0.f) * sc0;
        float o10 = fmaxf(acc[j][2] + bv.x, 0.f) * sc1;
        float o11 = fmaxf(acc[j][3] + bv.y, 0.f) * sc1;
        if (outh) {
            if (ok0) *(uint32_t*)(outh + row0 * HID + col) = packhf(o00, o01);
            if (ok1) *(uint32_t*)(outh + row1 * HID + col) = packhf(o10, o11);
        } else {
            if (ok0) *(float2*)(outf + row0 * HID + col) = make_float2(o00, o01);
            if (ok1) *(float2*)(outf + row1 * HID + col) = make_float2(o10, o11);
        }
    }
}

// ---------------- layer 2 (W2): rank-1 reconstruct gather + HMMA -> fp16 hfA ----------------
__global__ void __launch_bounds__(THREADS) k_layer_first(const float* __restrict__ W1,
                                                         const float* __restrict__ B1,
                                                         const float* __restrict__ bb) {
    extern __shared__ char smem[];
    uint32_t smem_base = smem_u32(smem);
    int br = blockIdx.y;
    int t = threadIdx.x;
    int wid = t >> 5, lane = t & 31;
    int nbase = blockIdx.x * BM;

    float* cdm = (float*)(smem + SM_CD);
    float* csm = (float*)(smem + SM_CS);
    if (t < BM) {
        int n = nbase + t;
        cdm[t] = (n < N_NODES) ? g_cd[br][n] : 0.f;
        csm[t] = (n < N_NODES) ? g_cs[br][n] : 0.f;
    }
    __syncthreads();

    {
        int kb = lane * 4;
        float4 w1  = *(const float4*)(W1 + kb);
        float4 b1v = *(const float4*)(B1 + kb);
        const float2* x1 = g_x1cs[br];
        const int* csr = g_csr[br];
        #pragma unroll
        for (int q = 0; q < 8; q++) {
            int nl = wid * 8 + q;
            int n  = nbase + nl;
            float4 acc = make_float4(0.f, 0.f, 0.f, 0.f);
            if (n < N_NODES) {
                int s = g_row[br][n], e = g_row[br][n + 1];
                int j = s;
                for (; j + 4 <= e; j += 4) {
                    float2 p0 = x1[csr[j]];
                    float2 p1 = x1[csr[j+1]];
                    float2 p2 = x1[csr[j+2]];
                    float2 p3 = x1[csr[j+3]];
                    acc.x += fmaxf(fmaf(p0.x, w1.x, b1v.x), 0.f) * p0.y
                           + fmaxf(fmaf(p1.x, w1.x, b1v.x), 0.f) * p1.y
                           + fmaxf(fmaf(p2.x, w1.x, b1v.x), 0.f) * p2.y
                           + fmaxf(fmaf(p3.x, w1.x, b1v.x), 0.f) * p3.y;
                    acc.y += fmaxf(fmaf(p0.x, w1.y, b1v.y), 0.f) * p0.y
                           + fmaxf(fmaf(p1.x, w1.y, b1v.y), 0.f) * p1.y
                           + fmaxf(fmaf(p2.x, w1.y, b1v.y), 0.f) * p2.y
                           + fmaxf(fmaf(p3.x, w1.y, b1v.y), 0.f) * p3.y;
                    acc.z += fmaxf(fmaf(p0.x, w1.z, b1v.z), 0.f) * p0.y
                           + fmaxf(fmaf(p1.x, w1.z, b1v.z), 0.f) * p1.y
                           + fmaxf(fmaf(p2.x, w1.z, b1v.z), 0.f) * p2.y
                           + fmaxf(fmaf(p3.x, w1.z, b1v.z), 0.f) * p3.y;
                    acc.w += fmaxf(fmaf(p0.x, w1.w, b1v.w), 0.f) * p0.y
                           + fmaxf(fmaf(p1.x, w1.w, b1v.w), 0.f) * p1.y
                           + fmaxf(fmaf(p2.x, w1.w, b1v.w), 0.f) * p2.y
                           + fmaxf(fmaf(p3.x, w1.w, b1v.w), 0.f) * p3.y;
                }
                for (; j < e; j++) {
                    float2 p = x1[csr[j]];
                    acc.x += fmaxf(fmaf(p.x, w1.x, b1v.x), 0.f) * p.y;
                    acc.y += fmaxf(fmaf(p.x, w1.y, b1v.y), 0.f) * p.y;
                    acc.z += fmaxf(fmaf(p.x, w1.z, b1v.z), 0.f) * p.y;
                    acc.w += fmaxf(fmaf(p.x, w1.w, b1v.w), 0.f) * p.y;
                }
            }
            float cdv = cdm[nl];
            store_A(smem, nl, lane, acc.x * cdv, acc.y * cdv, acc.z * cdv, acc.w * cdv);
        }
    }

    mma_gemm(smem, smem_base, 0, nbase, bb, csm, 1, g_hfA[br], nullptr, t);
}

// ---------------- layers 3/4: fp16 row gather (MLP-16) + HMMA ----------------
// lvl=0: in hfA -> out hfB (fp16, *cs), W idx 1 ; lvl=1: in hfB -> out hsO (fp32), W idx 2
__global__ void __launch_bounds__(THREADS) k_layer(int lvl, const float* __restrict__ bb) {
    extern __shared__ char smem[];
    uint32_t smem_base = smem_u32(smem);
    int br = blockIdx.y;
    int t = threadIdx.x;
    int wid = t >> 5, lane = t & 31;
    int nbase = blockIdx.x * BM;

    const uint2* in2 = (const uint2*)(lvl ? g_hfB[br] : g_hfA[br]);

    float* cdm = (float*)(smem + SM_CD);
    float* csm = (float*)(smem + SM_CS);
    if (t < BM) {
        int n = nbase + t;
        cdm[t] = (n < N_NODES) ? g_cd[br][n] : 0.f;
        csm[t] = (n < N_NODES) ? g_cs[br][n] : 0.f;
    }
    __syncthreads();

    {
        const int* csr = g_csr[br];
        #pragma unroll
        for (int q = 0; q < 8; q++) {
            int nl = wid * 8 + q;
            int n  = nbase + nl;
            float4 acc = make_float4(0.f, 0.f, 0.f, 0.f);
            if (n < N_NODES) {
                int s = g_row[br][n], e = g_row[br][n + 1];
                int j = s;
                // 16 edges in flight (MLP=16)
                for (; j + 16 <= e; j += 16) {
                    uint2 v[16];
                    #pragma unroll
                    for (int u = 0; u < 16; u++) v[u] = in2[csr[j + u] * 32 + lane];
                    float ax = 0.f, ay = 0.f, az = 0.f, aw = 0.f;
                    #pragma unroll
                    for (int u = 0; u < 16; u++) {
                        ax += h_lo(v[u].x); ay += h_hi(v[u].x);
                        az += h_lo(v[u].y); aw += h_hi(v[u].y);
                    }
                    acc.x += ax; acc.y += ay; acc.z += az; acc.w += aw;
                }
                // 8 edges in flight
                for (; j + 8 <= e; j += 8) {
                    uint2 v[8];
                    #pragma unroll
                    for (int u = 0; u < 8; u++) v[u] = in2[csr[j + u] * 32 + lane];
                    float ax = 0.f, ay = 0.f, az = 0.f, aw = 0.f;
                    #pragma unroll
                    for (int u = 0; u < 8; u++) {
                        ax += h_lo(v[u].x); ay += h_hi(v[u].x);
                        az += h_lo(v[u].y); aw += h_hi(v[u].y);
                    }
                    acc.x += ax; acc.y += ay; acc.z += az; acc.w += aw;
                }
                for (; j + 4 <= e; j += 4) {
                    uint2 v0 = in2[csr[j]     * 32 + lane];
                    uint2 v1 = in2[csr[j + 1] * 32 + lane];
                    uint2 v2 = in2[csr[j + 2] * 32 + lane];
                    uint2 v3 = in2[csr[j + 3] * 32 + lane];
                    acc.x += (h_lo(v0.x) + h_lo(v1.x)) + (h_lo(v2.x) + h_lo(v3.x));
                    acc.y += (h_hi(v0.x) + h_hi(v1.x)) + (h_hi(v2.x) + h_hi(v3.x));
                    acc.z += (h_lo(v0.y) + h_lo(v1.y)) + (h_lo(v2.y) + h_lo(v3.y));
                    acc.w += (h_hi(v0.y) + h_hi(v1.y)) + (h_hi(v2.y) + h_hi(v3.y));
                }
                for (; j < e; j++) {
                    uint2 v = in2[csr[j] * 32 + lane];
                    acc.x += h_lo(v.x); acc.y += h_hi(v.x);
                    acc.z += h_lo(v.y); acc.w += h_hi(v.y);
                }
            }
            float cdv = cdm[nl];
            store_A(smem, nl, lane, acc.x * cdv, acc.y * cdv, acc.z * cdv, acc.w * cdv);
        }
    }

    if (lvl == 0)
        mma_gemm(smem, smem_base, 1, nbase, bb, csm, 1, g_hfB[br], nullptr, t);
    else
        mma_gemm(smem, smem_base, 2, nbase, bb, csm, 0, nullptr, g_hsO[br], t);
}

// ---------------- pooling + head ----------------

__global__ void k_pool(const int* __restrict__ sg1, const int* __restrict__ sg2,
                       float* __restrict__ out) {
    int br = blockIdx.z;
    const int* seg = br ? sg2 : sg1;
    float* outg = out + br * N_GRAPHS * HID;
    const float* hs = g_hsO[br];
    int g = blockIdx.x, slice = blockIdx.y, j = threadIdx.x;
    int lo = 0, hi = N_NODES;
    while (lo < hi) { int m = (lo + hi) >> 1; if (seg[m] < g) lo = m + 1; else hi = m; }
    int start = lo;
    hi = N_NODES;
    while (lo < hi) { int m = (lo + hi) >> 1; if (seg[m] < g + 1) lo = m + 1; else hi = m; }
    int end = lo;
    int len = end - start;
    int s0 = start + (int)(((long long)len * slice) / NSPLIT);
    int s1 = start + (int)(((long long)len * (slice + 1)) / NSPLIT);
    float s = 0.f;
    for (int n = s0; n < s1; n++) s += hs[n * HID + j];
    if (s1 > s0) atomicAdd(&outg[g * HID + j], s);
}

__global__ void k_pooldiv(const int* __restrict__ sg1, const int* __restrict__ sg2,
                          float* __restrict__ out) {
    int br = blockIdx.y;
    const int* seg = br ? sg2 : sg1;
    float* outg = out + br * N_GRAPHS * HID;
    int g = blockIdx.x, j = threadIdx.x;
    int lo = 0, hi = N_NODES;
    while (lo < hi) { int m = (lo + hi) >> 1; if (seg[m] < g) lo = m + 1; else hi = m; }
    int start = lo;
    hi = N_NODES;
    while (lo < hi) { int m = (lo + hi) >> 1; if (seg[m] < g + 1) lo = m + 1; else hi = m; }
    float cnt = (float)(lo - start);
    outg[g * HID + j] /= fmaxf(cnt, 1.0f);
}

__global__ void k_logits(const float* __restrict__ hg, const float* __restrict__ Wc,
                         const float* __restrict__ bc, float* __restrict__ outl) {
    __shared__ float dsh[HID];
    int g = blockIdx.x, t = threadIdx.x;
    dsh[t] = fabsf(hg[g * HID + t] - hg[N_GRAPHS * HID + g * HID + t]);
    __syncthreads();
    if (t < N_CLASSES) {
        float a = bc[t];
        #pragma unroll 8
        for (int k = 0; k < HID; k++) a = fmaf(dsh[k], Wc[k * N_CLASSES + t], a);
        outl[g * N_CLASSES + t] = a;
    }
}

// ---------------- launch ----------------
extern "C" void kernel_launch(void* const* d_in, const int* in_sizes, int n_in,
                              void* d_out, int out_size) {
    const int* src1 = (const int*)d_in[0];
    const int* dst1 = (const int*)d_in[1];
    const int* seg1 = (const int*)d_in[2];
    const int* src2 = (const int*)d_in[3];
    const int* dst2 = (const int*)d_in[4];
    const int* seg2 = (const int*)d_in[5];
    const float* W1 = (const float*)d_in[6];
    const float* b1 = (const float*)d_in[7];
    const float* W2 = (const float*)d_in[8];
    const float* b2 = (const float*)d_in[9];
    const float* W3 = (const float*)d_in[10];
    const float* b3 = (const float*)d_in[11];
    const float* W4 = (const float*)d_in[12];
    const float* b4 = (const float*)d_in[13];
    const float* Wc = (const float*)d_in[14];
    const float* bc = (const float*)d_in[15];
    float* out = (float*)d_out;

    cudaFuncSetAttribute(k_layer_first, cudaFuncAttributeMaxDynamicSharedMemorySize, SMEM_TOT);
    cudaFuncSetAttribute(k_layer,       cudaFuncAttributeMaxDynamicSharedMemorySize, SMEM_TOT);

    k_init<<<dim3(NBLK, 2), 256>>>(out, W2, W3, W4);
    k_degree<<<dim3((N_EDGES + 255) / 256, 2), 256>>>(src1, dst1, src2, dst2);

    k_scan1<<<dim3(NBLK, 2), 256>>>();
    k_scan2<<<dim3(1, 2), 512>>>();
    k_scan3<<<dim3(NBLK, 2), 256>>>();
    k_fill<<<dim3((N_EDGES + 255) / 256, 2), 256>>>(src1, dst1, src2, dst2);
    k_x1<<<dim3(NBLK, 2), 256>>>();

    k_layer_first<<<dim3(LGRID, 2), THREADS, SMEM_TOT>>>(W1, b1, b2);
    k_layer<<<dim3(LGRID, 2), THREADS, SMEM_TOT>>>(0, b3);
    k_layer<<<dim3(LGRID, 2), THREADS, SMEM_TOT>>>(1, b4);

    k_pool<<<dim3(N_GRAPHS, NSPLIT, 2), HID>>>(seg1, seg2, out);
    k_pooldiv<<<dim3(N_GRAPHS, 2), HID>>>(seg1, seg2, out);
    k_logits<<<N_GRAPHS, HID>>>(out, Wc, bc, out + 2 * N_GRAPHS * HID);
}

// round 16
// speedup vs baseline: 1.0030x; 1.0030x over previous
#include <cuda_runtime.h>
#include <cuda_fp16.h>
#include <math.h>
#include <stdint.h>

#define N_NODES   100000
#define N_EDGES   1600000
#define N_GRAPHS  128
#define HID       128
#define N_CLASSES 10
#define NBLK      391            // ceil(N_NODES/256)
#define BM        64             // nodes per layer block (MMA M)
#define LGRID     ((N_NODES + BM - 1) / BM)   // 1563
#define THREADS   256
#define NSPLIT    16
#define KC        32             // W k-chunk size

#define PADA      272
#define PADW      80
#define SM_AH     0
#define SM_AL     17408
#define SM_WH     34816
#define SM_WL     45056
#define SM_CD     55296
#define SM_CS     55552
#define SMEM_TOT  55808

// ---------------- scratch ----------------
__device__ float  g_deg_out[2][N_NODES];
__device__ float  g_deg_in [2][N_NODES];
__device__ float  g_cs     [2][N_NODES];
__device__ float  g_cd     [2][N_NODES];
__device__ float  g_h1     [2][N_NODES];
__device__ float  g_agg1   [2][N_NODES];
__device__ float2 g_x1cs   [2][N_NODES];
__device__ int    g_rowtmp [2][N_NODES];
__device__ int    g_bsum   [2][512];
__device__ int    g_boff   [2][512];
__device__ int    g_row    [2][N_NODES + 1];
__device__ int    g_cursor [2][N_NODES];
__device__ int    g_csr    [2][N_EDGES];
__device__ __align__(16) unsigned short g_hfA[2][N_NODES * HID];
__device__ __align__(16) unsigned short g_hfB[2][N_NODES * HID];
__device__ __align__(16) unsigned short g_WtH[3][HID * HID];
__device__ __align__(16) unsigned short g_WtL[3][HID * HID];

// ---------------- helpers ----------------
__device__ __forceinline__ uint32_t smem_u32(const void* p) {
    uint32_t a;
    asm("{ .reg .u64 t; cvta.to.shared.u64 t, %1; cvt.u32.u64 %0, t; }" : "=r"(a) : "l"(p));
    return a;
}
__device__ __forceinline__ uint32_t packhf(float l, float h) {
    __half2 v = __floats2half2_rn(l, h);
    return *(uint32_t*)&v;
}
__device__ __forceinline__ float h_lo(uint32_t w) { __half2 v = *(__half2*)&w; return __low2float(v); }
__device__ __forceinline__ float h_hi(uint32_t w) { __half2 v = *(__half2*)&w; return __high2float(v); }

#define LDSM4(r0, r1, r2, r3, addr) \
    asm volatile("ldmatrix.sync.aligned.m8n8.x4.shared.b16 {%0,%1,%2,%3}, [%4];" \
        : "=r"(r0), "=r"(r1), "=r"(r2), "=r"(r3) : "r"(addr))

#define MMA16816(d, a0, a1, a2, a3, b0, b1) \
    asm volatile("mma.sync.aligned.m16n8k16.row.col.f32.f16.f16.f32 " \
        "{%0,%1,%2,%3}, {%4,%5,%6,%7}, {%8,%9}, {%0,%1,%2,%3};" \
        : "+f"((d)[0]), "+f"((d)[1]), "+f"((d)[2]), "+f"((d)[3]) \
        : "r"(a0), "r"(a1), "r"(a2), "r"(a3), "r"(b0), "r"(b1))

__device__ __forceinline__ void splithf(float v, __half& hi, __half& lo) {
    hi = __float2half_rn(v);
    lo = __float2half_rn(v - __half2float(hi));
}

// ---------------- prolog: fused zero + output-zero + W prep ----------------
__global__ void k_init(float* __restrict__ out,
                       const float* __restrict__ W2, const float* __restrict__ W3,
                       const float* __restrict__ W4) {
    int br = blockIdx.y;
    int i = blockIdx.x * blockDim.x + threadIdx.x;
    if (i < N_NODES) {
        g_deg_out[br][i] = 0.f;
        g_deg_in [br][i] = 0.f;
        g_agg1   [br][i] = 0.f;
    }
    int gid = br * (NBLK * 256) + i;
    if (gid < 2 * N_GRAPHS * HID) {
        out[gid] = 0.f;
    } else if (gid < 2 * N_GRAPHS * HID + 3 * HID * HID) {
        int idx2 = gid - 2 * N_GRAPHS * HID;
        int which = idx2 / (HID * HID);
        int idx = idx2 - which * (HID * HID);
        const float* W = (which == 0) ? W2 : (which == 1) ? W3 : W4;
        int n = idx >> 7, k = idx & 127;
        __half hh, hl;
        splithf(W[k * HID + n], hh, hl);
        g_WtH[which][idx] = *(unsigned short*)&hh;
        g_WtL[which][idx] = *(unsigned short*)&hl;
    }
}

__global__ void k_degree(const int* __restrict__ s1, const int* __restrict__ d1,
                         const int* __restrict__ s2, const int* __restrict__ d2) {
    int br = blockIdx.y;
    const int* src = br ? s2 : s1;
    const int* dst = br ? d2 : d1;
    int e = blockIdx.x * blockDim.x + threadIdx.x;
    if (e < N_EDGES) {
        atomicAdd(&g_deg_out[br][src[e]], 1.0f);
        atomicAdd(&g_deg_in [br][dst[e]], 1.0f);
    }
}

__global__ void k_scan1() {
    __shared__ int sh[256];
    int br = blockIdx.y;
    int t = threadIdx.x, b = blockIdx.x;
    int i = b * 256 + t;
    int v = 0;
    if (i < N_NODES) {
        float od = g_deg_out[br][i], id = g_deg_in[br][i];
        float cs = rsqrtf(fmaxf(od, 1.0f));
        float cd = rsqrtf(fmaxf(id, 1.0f));
        g_cs[br][i] = cs; g_cd[br][i] = cd;
        g_h1[br][i] = id * cs;
        v = __float2int_rn(id);
    }
    sh[t] = v;
    __syncthreads();
    #pragma unroll
    for (int off = 1; off < 256; off <<= 1) {
        int add = (t >= off) ? sh[t - off] : 0;
        __syncthreads();
        sh[t] += add;
        __syncthreads();
    }
    if (i < N_NODES) g_rowtmp[br][i] = sh[t] - v;
    if (t == 255) g_bsum[br][b] = sh[255];
}

__global__ void k_scan2() {
    __shared__ int sh[512];
    int br = blockIdx.y;
    int t = threadIdx.x;
    int v = (t < NBLK) ? g_bsum[br][t] : 0;
    sh[t] = v;
    __syncthreads();
    #pragma unroll
    for (int off = 1; off < 512; off <<= 1) {
        int add = (t >= off) ? sh[t - off] : 0;
        __syncthreads();
        sh[t] += add;
        __syncthreads();
    }
    g_boff[br][t] = sh[t] - v;
}

__global__ void k_scan3() {
    int br = blockIdx.y;
    int i = blockIdx.x * blockDim.x + threadIdx.x;
    if (i < N_NODES) {
        int r = g_rowtmp[br][i] + g_boff[br][i >> 8];
        g_row[br][i] = r;
        g_cursor[br][i] = r;
    }
    if (i == 0) g_row[br][N_NODES] = N_EDGES;
}

__global__ void k_fill(const int* __restrict__ s1, const int* __restrict__ d1,
                       const int* __restrict__ s2, const int* __restrict__ d2) {
    int br = blockIdx.y;
    const int* src = br ? s2 : s1;
    const int* dst = br ? d2 : d1;
    int e = blockIdx.x * blockDim.x + threadIdx.x;
    if (e < N_EDGES) {
        int s = src[e], d = dst[e];
        int pos = atomicAdd(&g_cursor[br][d], 1);
        g_csr[br][pos] = s;
        atomicAdd(&g_agg1[br][d], g_h1[br][s]);
    }
}

__global__ void k_x1() {
    int br = blockIdx.y;
    int n = blockIdx.x * blockDim.x + threadIdx.x;
    if (n < N_NODES)
        g_x1cs[br][n] = make_float2(g_agg1[br][n] * g_cd[br][n], g_cs[br][n]);
}

// ---------------- layer building blocks ----------------

__device__ __forceinline__ void store_A(char* smem, int nl, int lane,
                                        float v0, float v1, float v2, float v3) {
    __half h0, l0, h1, l1, h2, l2, h3, l3;
    splithf(v0, h0, l0); splithf(v1, h1, l1);
    splithf(v2, h2, l2); splithf(v3, h3, l3);
    uint32_t off = (uint32_t)(nl * PADA + lane * 8);
    *(uint2*)(smem + SM_AH + off) = make_uint2(packhf(__half2float(h0), __half2float(h1)),
                                               packhf(__half2float(h2), __half2float(h3)));
    *(uint2*)(smem + SM_AL + off) = make_uint2(packhf(__half2float(l0), __half2float(l1)),
                                               packhf(__half2float(l2), __half2float(l3)));
}

// split-A x split-W 3-term HMMA GEMM with W chunk staging + epilogue.
// outh != nullptr: fp16 out (applyCs). outh == nullptr: layer-4 fused pool —
// atomicAdd(float2) relu(acc+b) into outp[seg[row]*HID+col].
__device__ __forceinline__ void mma_gemm(char* smem, uint32_t smem_base, int l, int nbase,
                                         const float* __restrict__ bb,
                                         const float* csm, int applyCs,
                                         unsigned short* outh,
                                         const int* __restrict__ seg,
                                         float* __restrict__ outp, int t) {
    int warp = t >> 5, lane = t & 31;
    int mr = (warp & 3) * 16;
    int nb = (warp >> 2) * 64;

    float acc[8][4];
    #pragma unroll
    for (int j = 0; j < 8; j++)
        #pragma unroll
        for (int c = 0; c < 4; c++) acc[j][c] = 0.f;

    uint32_t aOff   = (uint32_t)((mr + (lane & 15)) * PADA + ((lane >> 4) << 4));
    uint32_t aHBase = smem_base + SM_AH + aOff;
    uint32_t aLBase = smem_base + SM_AL + aOff;
    uint32_t bRow   = (uint32_t)(nb + ((lane >> 4) << 3) + (lane & 7));
    uint32_t bCol   = (uint32_t)(((lane >> 3) & 1) << 4);

    const unsigned short* WH = g_WtH[l];
    const unsigned short* WL = g_WtL[l];

    #pragma unroll
    for (int kc = 0; kc < 4; kc++) {
        __syncthreads();
        #pragma unroll
        for (int i = 0; i < 2; i++) {
            int idx = t + i * 256;
            int row = idx >> 2, c = idx & 3;
            *(uint4*)(smem + SM_WH + row * PADW + c * 16) =
                *(const uint4*)(WH + row * HID + kc * KC + c * 8);
            *(uint4*)(smem + SM_WL + row * PADW + c * 16) =
                *(const uint4*)(WL + row * HID + kc * KC + c * 8);
        }
        __syncthreads();
        #pragma unroll
        for (int kk = 0; kk < 2; kk++) {
            int kglob = kc * KC + kk * 16;
            uint32_t a0, a1, a2, a3, e0, e1, e2, e3;
            LDSM4(a0, a1, a2, a3, aHBase + kglob * 2);
            LDSM4(e0, e1, e2, e3, aLBase + kglob * 2);
            #pragma unroll
            for (int j2 = 0; j2 < 4; j2++) {
                uint32_t boff = (bRow + j2 * 16) * PADW + bCol + kk * 32;
                uint32_t b0, b1, b2, b3;
                LDSM4(b0, b1, b2, b3, smem_base + SM_WH + boff);
                MMA16816(acc[j2 * 2],     a0, a1, a2, a3, b0, b1);
                MMA16816(acc[j2 * 2 + 1], a0, a1, a2, a3, b2, b3);
                MMA16816(acc[j2 * 2],     e0, e1, e2, e3, b0, b1);
                MMA16816(acc[j2 * 2 + 1], e0, e1, e2, e3, b2, b3);
                uint32_t c0, c1, c2, c3;
                LDSM4(c0, c1, c2, c3, smem_base + SM_WL + boff);
                MMA16816(acc[j2 * 2],     a0, a1, a2, a3, c0, c1);
                MMA16816(acc[j2 * 2 + 1], a0, a1, a2, a3, c2, c3);
            }
        }
    }

    int lm = lane >> 2;
    int ln = (lane & 3) * 2;
    int r0l = mr + lm;
    int row0 = nbase + r0l, row1 = row0 + 8;
    bool ok0 = row0 < N_NODES, ok1 = row1 < N_NODES;

    if (outh) {
        float sc0 = applyCs ? csm[r0l]     : 1.0f;
        float sc1 = applyCs ? csm[r0l + 8] : 1.0f;
        #pragma unroll
        for (int j = 0; j < 8; j++) {
            int col = nb + j * 8 + ln;
            float2 bv = *(const float2*)&bb[col];
            float o00 = fmaxf(acc[j][0] + bv.x, 0.f) * sc0;
            float o01 = fmaxf(acc[j][1] + bv.y, 0.f) * sc0;
            float o10 = fmaxf(acc[j][2] + bv.x, 0.f) * sc1;
            float o11 = fmaxf(acc[j][3] + bv.y, 0.f) * sc1;
            if (ok0) *(uint32_t*)(outh + row0 * HID + col) = packhf(o00, o01);
            if (ok1) *(uint32_t*)(outh + row1 * HID + col) = packhf(o10, o11);
        }
    } else {
        // layer-4 fused pooling: accumulate relu(acc+b) into per-graph sums
        int g0 = ok0 ? seg[row0] : 0;
        int g1 = ok1 ? seg[row1] : 0;
        #pragma unroll
        for (int j = 0; j < 8; j++) {
            int col = nb + j * 8 + ln;
            float2 bv = *(const float2*)&bb[col];
            if (ok0) {
                float2 o = make_float2(fmaxf(acc[j][0] + bv.x, 0.f),
                                       fmaxf(acc[j][1] + bv.y, 0.f));
                atomicAdd((float2*)&outp[g0 * HID + col], o);
            }
            if (ok1) {
                float2 o = make_float2(fmaxf(acc[j][2] + bv.x, 0.f),
                                       fmaxf(acc[j][3] + bv.y, 0.f));
                atomicAdd((float2*)&outp[g1 * HID + col], o);
            }
        }
    }
}

// ---------------- layer 2 (W2): rank-1 reconstruct gather + HMMA -> fp16 hfA ----------------
__global__ void __launch_bounds__(THREADS) k_layer_first(const float* __restrict__ W1,
                                                         const float* __restrict__ B1,
                                                         const float* __restrict__ bb) {
    extern __shared__ char smem[];
    uint32_t smem_base = smem_u32(smem);
    int br = blockIdx.y;
    int t = threadIdx.x;
    int wid = t >> 5, lane = t & 31;
    int nbase = blockIdx.x * BM;

    float* cdm = (float*)(smem + SM_CD);
    float* csm = (float*)(smem + SM_CS);
    if (t < BM) {
        int n = nbase + t;
        cdm[t] = (n < N_NODES) ? g_cd[br][n] : 0.f;
        csm[t] = (n < N_NODES) ? g_cs[br][n] : 0.f;
    }
    __syncthreads();

    {
        int kb = lane * 4;
        float4 w1  = *(const float4*)(W1 + kb);
        float4 b1v = *(const float4*)(B1 + kb);
        const float2* x1 = g_x1cs[br];
        const int* csr = g_csr[br];
        #pragma unroll
        for (int q = 0; q < 8; q++) {
            int nl = wid * 8 + q;
            int n  = nbase + nl;
            float4 acc = make_float4(0.f, 0.f, 0.f, 0.f);
            if (n < N_NODES) {
                int s = g_row[br][n], e = g_row[br][n + 1];
                int j = s;
                for (; j + 4 <= e; j += 4) {
                    float2 p0 = x1[csr[j]];
                    float2 p1 = x1[csr[j+1]];
                    float2 p2 = x1[csr[j+2]];
                    float2 p3 = x1[csr[j+3]];
                    acc.x += fmaxf(fmaf(p0.x, w1.x, b1v.x), 0.f) * p0.y
                           + fmaxf(fmaf(p1.x, w1.x, b1v.x), 0.f) * p1.y
                           + fmaxf(fmaf(p2.x, w1.x, b1v.x), 0.f) * p2.y
                           + fmaxf(fmaf(p3.x, w1.x, b1v.x), 0.f) * p3.y;
                    acc.y += fmaxf(fmaf(p0.x, w1.y, b1v.y), 0.f) * p0.y
                           + fmaxf(fmaf(p1.x, w1.y, b1v.y), 0.f) * p1.y
                           + fmaxf(fmaf(p2.x, w1.y, b1v.y), 0.f) * p2.y
                           + fmaxf(fmaf(p3.x, w1.y, b1v.y), 0.f) * p3.y;
                    acc.z += fmaxf(fmaf(p0.x, w1.z, b1v.z), 0.f) * p0.y
                           + fmaxf(fmaf(p1.x, w1.z, b1v.z), 0.f) * p1.y
                           + fmaxf(fmaf(p2.x, w1.z, b1v.z), 0.f) * p2.y
                           + fmaxf(fmaf(p3.x, w1.z, b1v.z), 0.f) * p3.y;
                    acc.w += fmaxf(fmaf(p0.x, w1.w, b1v.w), 0.f) * p0.y
                           + fmaxf(fmaf(p1.x, w1.w, b1v.w), 0.f) * p1.y
                           + fmaxf(fmaf(p2.x, w1.w, b1v.w), 0.f) * p2.y
                           + fmaxf(fmaf(p3.x, w1.w, b1v.w), 0.f) * p3.y;
                }
                for (; j < e; j++) {
                    float2 p = x1[csr[j]];
                    acc.x += fmaxf(fmaf(p.x, w1.x, b1v.x), 0.f) * p.y;
                    acc.y += fmaxf(fmaf(p.x, w1.y, b1v.y), 0.f) * p.y;
                    acc.z += fmaxf(fmaf(p.x, w1.z, b1v.z), 0.f) * p.y;
                    acc.w += fmaxf(fmaf(p.x, w1.w, b1v.w), 0.f) * p.y;
                }
            }
            float cdv = cdm[nl];
            store_A(smem, nl, lane, acc.x * cdv, acc.y * cdv, acc.z * cdv, acc.w * cdv);
        }
    }

    mma_gemm(smem, smem_base, 0, nbase, bb, csm, 1, g_hfA[br], nullptr, nullptr, t);
}

// ---------------- layers 3/4: fp16 row gather (MLP-8) + HMMA ----------------
// lvl=0: in hfA -> out hfB (fp16, *cs). lvl=1: in hfB -> fused pool into out.
__global__ void __launch_bounds__(THREADS) k_layer(int lvl, const float* __restrict__ bb,
                                                   const int* __restrict__ sg1,
                                                   const int* __restrict__ sg2,
                                                   float* __restrict__ out) {
    extern __shared__ char smem[];
    uint32_t smem_base = smem_u32(smem);
    int br = blockIdx.y;
    int t = threadIdx.x;
    int wid = t >> 5, lane = t & 31;
    int nbase = blockIdx.x * BM;

    const uint2* in2 = (const uint2*)(lvl ? g_hfB[br] : g_hfA[br]);

    float* cdm = (float*)(smem + SM_CD);
    float* csm = (float*)(smem + SM_CS);
    if (t < BM) {
        int n = nbase + t;
        cdm[t] = (n < N_NODES) ? g_cd[br][n] : 0.f;
        csm[t] = (n < N_NODES) ? g_cs[br][n] : 0.f;
    }
    __syncthreads();

    {
        const int* csr = g_csr[br];
        #pragma unroll
        for (int q = 0; q < 8; q++) {
            int nl = wid * 8 + q;
            int n  = nbase + nl;
            float4 acc = make_float4(0.f, 0.f, 0.f, 0.f);
            if (n < N_NODES) {
                int s = g_row[br][n], e = g_row[br][n + 1];
                int j = s;
                for (; j + 8 <= e; j += 8) {
                    int i0 = csr[j],   i1 = csr[j+1], i2 = csr[j+2], i3 = csr[j+3];
                    int i4 = csr[j+4], i5 = csr[j+5], i6 = csr[j+6], i7 = csr[j+7];
                    uint2 v0 = in2[i0 * 32 + lane];
                    uint2 v1 = in2[i1 * 32 + lane];
                    uint2 v2 = in2[i2 * 32 + lane];
                    uint2 v3 = in2[i3 * 32 + lane];
                    uint2 v4 = in2[i4 * 32 + lane];
                    uint2 v5 = in2[i5 * 32 + lane];
                    uint2 v6 = in2[i6 * 32 + lane];
                    uint2 v7 = in2[i7 * 32 + lane];
                    acc.x += ((h_lo(v0.x) + h_lo(v1.x)) + (h_lo(v2.x) + h_lo(v3.x)))
                           + ((h_lo(v4.x) + h_lo(v5.x)) + (h_lo(v6.x) + h_lo(v7.x)));
                    acc.y += ((h_hi(v0.x) + h_hi(v1.x)) + (h_hi(v2.x) + h_hi(v3.x)))
                           + ((h_hi(v4.x) + h_hi(v5.x)) + (h_hi(v6.x) + h_hi(v7.x)));
                    acc.z += ((h_lo(v0.y) + h_lo(v1.y)) + (h_lo(v2.y) + h_lo(v3.y)))
                           + ((h_lo(v4.y) + h_lo(v5.y)) + (h_lo(v6.y) + h_lo(v7.y)));
                    acc.w += ((h_hi(v0.y) + h_hi(v1.y)) + (h_hi(v2.y) + h_hi(v3.y)))
                           + ((h_hi(v4.y) + h_hi(v5.y)) + (h_hi(v6.y) + h_hi(v7.y)));
                }
                for (; j + 4 <= e; j += 4) {
                    int i0 = csr[j], i1 = csr[j+1], i2 = csr[j+2], i3 = csr[j+3];
                    uint2 v0 = in2[i0 * 32 + lane];
                    uint2 v1 = in2[i1 * 32 + lane];
                    uint2 v2 = in2[i2 * 32 + lane];
                    uint2 v3 = in2[i3 * 32 + lane];
                    acc.x += (h_lo(v0.x) + h_lo(v1.x)) + (h_lo(v2.x) + h_lo(v3.x));
                    acc.y += (h_hi(v0.x) + h_hi(v1.x)) + (h_hi(v2.x) + h_hi(v3.x));
                    acc.z += (h_lo(v0.y) + h_lo(v1.y)) + (h_lo(v2.y) + h_lo(v3.y));
                    acc.w += (h_hi(v0.y) + h_hi(v1.y)) + (h_hi(v2.y) + h_hi(v3.y));
                }
                for (; j < e; j++) {
                    uint2 v = in2[csr[j] * 32 + lane];
                    acc.x += h_lo(v.x); acc.y += h_hi(v.x);
                    acc.z += h_lo(v.y); acc.w += h_hi(v.y);
                }
            }
            float cdv = cdm[nl];
            store_A(smem, nl, lane, acc.x * cdv, acc.y * cdv, acc.z * cdv, acc.w * cdv);
        }
    }

    if (lvl == 0) {
        mma_gemm(smem, smem_base, 1, nbase, bb, csm, 1, g_hfB[br], nullptr, nullptr, t);
    } else {
        const int* seg = br ? sg2 : sg1;
        float* outp = out + br * N_GRAPHS * HID;
        mma_gemm(smem, smem_base, 2, nbase, bb, csm, 0, nullptr, seg, outp, t);
    }
}

// ---------------- pool finalize + head ----------------

__global__ void k_pooldiv(const int* __restrict__ sg1, const int* __restrict__ sg2,
                          float* __restrict__ out) {
    int br = blockIdx.y;
    const int* seg = br ? sg2 : sg1;
    float* outg = out + br * N_GRAPHS * HID;
    int g = blockIdx.x, j = threadIdx.x;
    int lo = 0, hi = N_NODES;
    while (lo < hi) { int m = (lo + hi) >> 1; if (seg[m] < g) lo = m + 1; else hi = m; }
    int start = lo;
    hi = N_NODES;
    while (lo < hi) { int m = (lo + hi) >> 1; if (seg[m] < g + 1) lo = m + 1; else hi = m; }
    float cnt = (float)(lo - start);
    outg[g * HID + j] /= fmaxf(cnt, 1.0f);
}

__global__ void k_logits(const float* __restrict__ hg, const float* __restrict__ Wc,
                         const float* __restrict__ bc, float* __restrict__ outl) {
    __shared__ float dsh[HID];
    int g = blockIdx.x, t = threadIdx.x;
    dsh[t] = fabsf(hg[g * HID + t] - hg[N_GRAPHS * HID + g * HID + t]);
    __syncthreads();
    if (t < N_CLASSES) {
        float a = bc[t];
        #pragma unroll 8
        for (int k = 0; k < HID; k++) a = fmaf(dsh[k], Wc[k * N_CLASSES + t], a);
        outl[g * N_CLASSES + t] = a;
    }
}

// ---------------- launch ----------------
extern "C" void kernel_launch(void* const* d_in, const int* in_sizes, int n_in,
                              void* d_out, int out_size) {
    const int* src1 = (const int*)d_in[0];
    const int* dst1 = (const int*)d_in[1];
    const int* seg1 = (const int*)d_in[2];
    const int* src2 = (const int*)d_in[3];
    const int* dst2 = (const int*)d_in[4];
    const int* seg2 = (const int*)d_in[5];
    const float* W1 = (const float*)d_in[6];
    const float* b1 = (const float*)d_in[7];
    const float* W2 = (const float*)d_in[8];
    const float* b2 = (const float*)d_in[9];
    const float* W3 = (const float*)d_in[10];
    const float* b3 = (const float*)d_in[11];
    const float* W4 = (const float*)d_in[12];
    const float* b4 = (const float*)d_in[13];
    const float* Wc = (const float*)d_in[14];
    const float* bc = (const float*)d_in[15];
    float* out = (float*)d_out;

    cudaFuncSetAttribute(k_layer_first, cudaFuncAttributeMaxDynamicSharedMemorySize, SMEM_TOT);
    cudaFuncSetAttribute(k_layer,       cudaFuncAttributeMaxDynamicSharedMemorySize, SMEM_TOT);

    k_init<<<dim3(NBLK, 2), 256>>>(out, W2, W3, W4);
    k_degree<<<dim3((N_EDGES + 255) / 256, 2), 256>>>(src1, dst1, src2, dst2);

    k_scan1<<<dim3(NBLK, 2), 256>>>();
    k_scan2<<<dim3(1, 2), 512>>>();
    k_scan3<<<dim3(NBLK, 2), 256>>>();
    k_fill<<<dim3((N_EDGES + 255) / 256, 2), 256>>>(src1, dst1, src2, dst2);
    k_x1<<<dim3(NBLK, 2), 256>>>();

    k_layer_first<<<dim3(LGRID, 2), THREADS, SMEM_TOT>>>(W1, b1, b2);
    k_layer<<<dim3(LGRID, 2), THREADS, SMEM_TOT>>>(0, b3, seg1, seg2, out);
    k_layer<<<dim3(LGRID, 2), THREADS, SMEM_TOT>>>(1, b4, seg1, seg2, out);

    k_pooldiv<<<dim3(N_GRAPHS, 2), HID>>>(seg1, seg2, out);
    k_logits<<<N_GRAPHS, HID>>>(out, Wc, bc, out + 2 * N_GRAPHS * HID);
}

// round 17
// speedup vs baseline: 1.0733x; 1.0700x over previous
#include <cuda_runtime.h>
#include <cuda_fp16.h>
#include <math.h>
#include <stdint.h>

#define N_NODES   100000
#define N_EDGES   1600000
#define N_GRAPHS  128
#define HID       128
#define N_CLASSES 10
#define NBLK      391            // ceil(N_NODES/256)
#define BM        64             // nodes per layer block (MMA M)
#define LGRID     ((N_NODES + BM - 1) / BM)   // 1563
#define THREADS   256
#define NSPLIT    16             // pool node-range splits per graph
#define KC        32             // W k-chunk size

// A tile rows: 128 fp16 + 8 pad = 272 B (stride 68 words -> conflict-free LDSM)
#define PADA      272
// W chunk rows: 32 fp16 + 8 pad = 80 B (stride 20 words -> conflict-free LDSM)
#define PADW      80
// dynamic smem layout (bytes)
#define SM_AH     0                      // A_hi: 64 x 272 = 17408
#define SM_AL     17408                  // A_lo: 17408
#define SM_WH     34816                  // W_hi chunk: 128 x 80 = 10240
#define SM_WL     45056                  // W_lo chunk: 10240
#define SM_CD     55296                  // cdm[64]
#define SM_CS     55552                  // csm[64]
#define SMEM_TOT  55808

// ---------------- scratch (static __device__, no runtime alloc) ----------------
__device__ float  g_deg_out[2][N_NODES];
__device__ float  g_deg_in [2][N_NODES];
__device__ float  g_cs     [2][N_NODES];
__device__ float  g_cd     [2][N_NODES];
__device__ float  g_h1     [2][N_NODES];
__device__ float  g_agg1   [2][N_NODES];       // layer-1 scalar aggregation (fused into fill)
__device__ float2 g_x1cs   [2][N_NODES];       // {agg1*cd, cs}
__device__ int    g_rowtmp [2][N_NODES];
__device__ int    g_bsum   [2][512];
__device__ int    g_boff   [2][512];
__device__ int    g_row    [2][N_NODES + 1];
__device__ int    g_cursor [2][N_NODES];
__device__ int    g_csr    [2][N_EDGES];
__device__ __align__(16) unsigned short g_hfA[2][N_NODES * HID];  // fp16 features
__device__ __align__(16) unsigned short g_hfB[2][N_NODES * HID];
__device__ float  g_hsO    [2][N_NODES * HID];  // layer-4 fp32 output (pool input)
__device__ __align__(16) unsigned short g_WtH[3][HID * HID];  // W^T fp16 hi
__device__ __align__(16) unsigned short g_WtL[3][HID * HID];  // W^T fp16 lo (residual)

// ---------------- helpers ----------------
__device__ __forceinline__ uint32_t smem_u32(const void* p) {
    uint32_t a;
    asm("{ .reg .u64 t; cvta.to.shared.u64 t, %1; cvt.u32.u64 %0, t; }" : "=r"(a) : "l"(p));
    return a;
}
__device__ __forceinline__ uint32_t packhf(float l, float h) {
    __half2 v = __floats2half2_rn(l, h);
    return *(uint32_t*)&v;
}
__device__ __forceinline__ float h_lo(uint32_t w) { __half2 v = *(__half2*)&w; return __low2float(v); }
__device__ __forceinline__ float h_hi(uint32_t w) { __half2 v = *(__half2*)&w; return __high2float(v); }

#define LDSM4(r0, r1, r2, r3, addr) \
    asm volatile("ldmatrix.sync.aligned.m8n8.x4.shared.b16 {%0,%1,%2,%3}, [%4];" \
        : "=r"(r0), "=r"(r1), "=r"(r2), "=r"(r3) : "r"(addr))

#define MMA16816(d, a0, a1, a2, a3, b0, b1) \
    asm volatile("mma.sync.aligned.m16n8k16.row.col.f32.f16.f16.f32 " \
        "{%0,%1,%2,%3}, {%4,%5,%6,%7}, {%8,%9}, {%0,%1,%2,%3};" \
        : "+f"((d)[0]), "+f"((d)[1]), "+f"((d)[2]), "+f"((d)[3]) \
        : "r"(a0), "r"(a1), "r"(a2), "r"(a3), "r"(b0), "r"(b1))

__device__ __forceinline__ void splithf(float v, __half& hi, __half& lo) {
    hi = __float2half_rn(v);
    lo = __float2half_rn(v - __half2float(hi));
}

// ---------------- small kernels ----------------

__global__ void k_zero_out(float* __restrict__ out) {
    int i = blockIdx.x * blockDim.x + threadIdx.x;
    out[i] = 0.f;
}

__global__ void k_zero_small() {
    int br = blockIdx.y;
    int i = blockIdx.x * blockDim.x + threadIdx.x;
    if (i < N_NODES) {
        g_deg_out[br][i] = 0.f;
        g_deg_in [br][i] = 0.f;
        g_agg1   [br][i] = 0.f;
    }
}

__global__ void k_degree(const int* __restrict__ s1, const int* __restrict__ d1,
                         const int* __restrict__ s2, const int* __restrict__ d2) {
    int br = blockIdx.y;
    const int* src = br ? s2 : s1;
    const int* dst = br ? d2 : d1;
    int e = blockIdx.x * blockDim.x + threadIdx.x;
    if (e < N_EDGES) {
        atomicAdd(&g_deg_out[br][src[e]], 1.0f);
        atomicAdd(&g_deg_in [br][dst[e]], 1.0f);
    }
}

// transpose + split-fp16 quantize W2/W3/W4 -> g_WtH/g_WtL [b][n*HID+k]
__global__ void k_prepW(const float* __restrict__ W2, const float* __restrict__ W3,
                        const float* __restrict__ W4) {
    const float* W = (blockIdx.x == 0) ? W2 : (blockIdx.x == 1) ? W3 : W4;
    unsigned short* oh = g_WtH[blockIdx.x];
    unsigned short* ol = g_WtL[blockIdx.x];
    for (int idx = threadIdx.x; idx < HID * HID; idx += blockDim.x) {
        int n = idx >> 7, k = idx & 127;
        __half hh, hl;
        splithf(W[k * HID + n], hh, hl);
        oh[idx] = *(unsigned short*)&hh;
        ol[idx] = *(unsigned short*)&hl;
    }
}

__global__ void k_scan1() {
    __shared__ int sh[256];
    int br = blockIdx.y;
    int t = threadIdx.x, b = blockIdx.x;
    int i = b * 256 + t;
    int v = 0;
    if (i < N_NODES) {
        float od = g_deg_out[br][i], id = g_deg_in[br][i];
        float cs = rsqrtf(fmaxf(od, 1.0f));
        float cd = rsqrtf(fmaxf(id, 1.0f));
        g_cs[br][i] = cs; g_cd[br][i] = cd;
        g_h1[br][i] = id * cs;
        v = __float2int_rn(id);
    }
    sh[t] = v;
    __syncthreads();
    #pragma unroll
    for (int off = 1; off < 256; off <<= 1) {
        int add = (t >= off) ? sh[t - off] : 0;
        __syncthreads();
        sh[t] += add;
        __syncthreads();
    }
    if (i < N_NODES) g_rowtmp[br][i] = sh[t] - v;
    if (t == 255) g_bsum[br][b] = sh[255];
}

__global__ void k_scan2() {
    __shared__ int sh[512];
    int br = blockIdx.y;
    int t = threadIdx.x;
    int v = (t < NBLK) ? g_bsum[br][t] : 0;
    sh[t] = v;
    __syncthreads();
    #pragma unroll
    for (int off = 1; off < 512; off <<= 1) {
        int add = (t >= off) ? sh[t - off] : 0;
        __syncthreads();
        sh[t] += add;
        __syncthreads();
    }
    g_boff[br][t] = sh[t] - v;
}

__global__ void k_scan3() {
    int br = blockIdx.y;
    int i = blockIdx.x * blockDim.x + threadIdx.x;
    if (i < N_NODES) {
        int r = g_rowtmp[br][i] + g_boff[br][i >> 8];
        g_row[br][i] = r;
        g_cursor[br][i] = r;
    }
    if (i == 0) g_row[br][N_NODES] = N_EDGES;
}

// CSR fill + fused layer-1 scalar aggregation
__global__ void k_fill(const int* __restrict__ s1, const int* __restrict__ d1,
                       const int* __restrict__ s2, const int* __restrict__ d2) {
    int br = blockIdx.y;
    const int* src = br ? s2 : s1;
    const int* dst = br ? d2 : d1;
    int e = blockIdx.x * blockDim.x + threadIdx.x;
    if (e < N_EDGES) {
        int s = src[e], d = dst[e];
        int pos = atomicAdd(&g_cursor[br][d], 1);
        g_csr[br][pos] = s;
        atomicAdd(&g_agg1[br][d], g_h1[br][s]);
    }
}

// finalize {x1 = agg1*cd, cs}
__global__ void k_x1() {
    int br = blockIdx.y;
    int n = blockIdx.x * blockDim.x + threadIdx.x;
    if (n < N_NODES)
        g_x1cs[br][n] = make_float2(g_agg1[br][n] * g_cd[br][n], g_cs[br][n]);
}

// ---------------- layer building blocks ----------------

// store split-A: node nl (0..63), k-group lane*4, fp32 values v0..v3
__device__ __forceinline__ void store_A(char* smem, int nl, int lane,
                                        float v0, float v1, float v2, float v3) {
    __half h0, l0, h1, l1, h2, l2, h3, l3;
    splithf(v0, h0, l0); splithf(v1, h1, l1);
    splithf(v2, h2, l2); splithf(v3, h3, l3);
    uint32_t off = (uint32_t)(nl * PADA + lane * 8);
    *(uint2*)(smem + SM_AH + off) = make_uint2(packhf(__half2float(h0), __half2float(h1)),
                                               packhf(__half2float(h2), __half2float(h3)));
    *(uint2*)(smem + SM_AL + off) = make_uint2(packhf(__half2float(l0), __half2float(l1)),
                                               packhf(__half2float(l2), __half2float(l3)));
}

// split-A x split-W 3-term HMMA GEMM with W chunk staging + epilogue.
// warp tile: m16 rows ((warp&3)*16) x n64 cols ((warp>>2)*64)
__device__ __forceinline__ void mma_gemm(char* smem, uint32_t smem_base, int l, int nbase,
                                         const float* __restrict__ bb,
                                         const float* csm, int applyCs,
                                         unsigned short* outh, float* outf, int t) {
    int warp = t >> 5, lane = t & 31;
    int mr = (warp & 3) * 16;
    int nb = (warp >> 2) * 64;

    float acc[8][4];
    #pragma unroll
    for (int j = 0; j < 8; j++)
        #pragma unroll
        for (int c = 0; c < 4; c++) acc[j][c] = 0.f;

    uint32_t aOff   = (uint32_t)((mr + (lane & 15)) * PADA + ((lane >> 4) << 4));
    uint32_t aHBase = smem_base + SM_AH + aOff;
    uint32_t aLBase = smem_base + SM_AL + aOff;
    uint32_t bRow   = (uint32_t)(nb + ((lane >> 4) << 3) + (lane & 7));
    uint32_t bCol   = (uint32_t)(((lane >> 3) & 1) << 4);

    const unsigned short* WH = g_WtH[l];
    const unsigned short* WL = g_WtL[l];

    #pragma unroll
    for (int kc = 0; kc < 4; kc++) {
        __syncthreads();
        // stage W chunk [128 n][32 k] hi+lo
        #pragma unroll
        for (int i = 0; i < 2; i++) {
            int idx = t + i * 256;          // 512 uint4 per tile
            int row = idx >> 2, c = idx & 3;
            *(uint4*)(smem + SM_WH + row * PADW + c * 16) =
                *(const uint4*)(WH + row * HID + kc * KC + c * 8);
            *(uint4*)(smem + SM_WL + row * PADW + c * 16) =
                *(const uint4*)(WL + row * HID + kc * KC + c * 8);
        }
        __syncthreads();
        #pragma unroll
        for (int kk = 0; kk < 2; kk++) {
            int kglob = kc * KC + kk * 16;
            uint32_t a0, a1, a2, a3, e0, e1, e2, e3;
            LDSM4(a0, a1, a2, a3, aHBase + kglob * 2);
            LDSM4(e0, e1, e2, e3, aLBase + kglob * 2);
            #pragma unroll
            for (int j2 = 0; j2 < 4; j2++) {
                uint32_t boff = (bRow + j2 * 16) * PADW + bCol + kk * 32;
                uint32_t b0, b1, b2, b3;
                LDSM4(b0, b1, b2, b3, smem_base + SM_WH + boff);
                MMA16816(acc[j2 * 2],     a0, a1, a2, a3, b0, b1);
                MMA16816(acc[j2 * 2 + 1], a0, a1, a2, a3, b2, b3);
                MMA16816(acc[j2 * 2],     e0, e1, e2, e3, b0, b1);
                MMA16816(acc[j2 * 2 + 1], e0, e1, e2, e3, b2, b3);
                uint32_t c0, c1, c2, c3;
                LDSM4(c0, c1, c2, c3, smem_base + SM_WL + boff);
                MMA16816(acc[j2 * 2],     a0, a1, a2, a3, c0, c1);
                MMA16816(acc[j2 * 2 + 1], a0, a1, a2, a3, c2, c3);
            }
        }
    }

    int lm = lane >> 2;
    int ln = (lane & 3) * 2;
    int r0l = mr + lm;
    int row0 = nbase + r0l, row1 = row0 + 8;
    float sc0 = applyCs ? csm[r0l]     : 1.0f;
    float sc1 = applyCs ? csm[r0l + 8] : 1.0f;
    bool ok0 = row0 < N_NODES, ok1 = row1 < N_NODES;

    #pragma unroll
    for (int j = 0; j < 8; j++) {
        int col = nb + j * 8 + ln;
        float2 bv = *(const float2*)&bb[col];
        float o00 = fmaxf(acc[j][0] + bv.x, 0.f) * sc0;
        float o01 = fmaxf(acc[j][1] + bv.y, 0.f) * sc0;
        float o10 = fmaxf(acc[j][2] + bv.x, 0.f) * sc1;
        float o11 = fmaxf(acc[j][3] + bv.y, 0.f) * sc1;
        if (outh) {
            if (ok0) *(uint32_t*)(outh + row0 * HID + col) = packhf(o00, o01);
            if (ok1) *(uint32_t*)(outh + row1 * HID + col) = packhf(o10, o11);
        } else {
            if (ok0) *(float2*)(outf + row0 * HID + col) = make_float2(o00, o01);
            if (ok1) *(float2*)(outf + row1 * HID + col) = make_float2(o10, o11);
        }
    }
}

// ---------------- layer 2 (W2): rank-1 reconstruct gather + HMMA -> fp16 hfA ----------------
__global__ void __launch_bounds__(THREADS, 4) k_layer_first(const float* __restrict__ W1,
                                                            const float* __restrict__ B1,
                                                            const float* __restrict__ bb) {
    extern __shared__ char smem[];
    uint32_t smem_base = smem_u32(smem);
    int br = blockIdx.y;
    int t = threadIdx.x;
    int wid = t >> 5, lane = t & 31;
    int nbase = blockIdx.x * BM;

    float* cdm = (float*)(smem + SM_CD);
    float* csm = (float*)(smem + SM_CS);
    if (t < BM) {
        int n = nbase + t;
        cdm[t] = (n < N_NODES) ? g_cd[br][n] : 0.f;
        csm[t] = (n < N_NODES) ? g_cs[br][n] : 0.f;
    }
    __syncthreads();

    {
        int kb = lane * 4;
        float4 w1  = *(const float4*)(W1 + kb);
        float4 b1v = *(const float4*)(B1 + kb);
        const float2* x1 = g_x1cs[br];
        const int* csr = g_csr[br];
        #pragma unroll
        for (int q = 0; q < 8; q++) {
            int nl = wid * 8 + q;
            int n  = nbase + nl;
            float4 acc = make_float4(0.f, 0.f, 0.f, 0.f);
            if (n < N_NODES) {
                int s = g_row[br][n], e = g_row[br][n + 1];
                int j = s;
                for (; j + 4 <= e; j += 4) {
                    float2 p0 = x1[csr[j]];
                    float2 p1 = x1[csr[j+1]];
                    float2 p2 = x1[csr[j+2]];
                    float2 p3 = x1[csr[j+3]];
                    acc.x += fmaxf(fmaf(p0.x, w1.x, b1v.x), 0.f) * p0.y
                           + fmaxf(fmaf(p1.x, w1.x, b1v.x), 0.f) * p1.y
                           + fmaxf(fmaf(p2.x, w1.x, b1v.x), 0.f) * p2.y
                           + fmaxf(fmaf(p3.x, w1.x, b1v.x), 0.f) * p3.y;
                    acc.y += fmaxf(fmaf(p0.x, w1.y, b1v.y), 0.f) * p0.y
                           + fmaxf(fmaf(p1.x, w1.y, b1v.y), 0.f) * p1.y
                           + fmaxf(fmaf(p2.x, w1.y, b1v.y), 0.f) * p2.y
                           + fmaxf(fmaf(p3.x, w1.y, b1v.y), 0.f) * p3.y;
                    acc.z += fmaxf(fmaf(p0.x, w1.z, b1v.z), 0.f) * p0.y
                           + fmaxf(fmaf(p1.x, w1.z, b1v.z), 0.f) * p1.y
                           + fmaxf(fmaf(p2.x, w1.z, b1v.z), 0.f) * p2.y
                           + fmaxf(fmaf(p3.x, w1.z, b1v.z), 0.f) * p3.y;
                    acc.w += fmaxf(fmaf(p0.x, w1.w, b1v.w), 0.f) * p0.y
                           + fmaxf(fmaf(p1.x, w1.w, b1v.w), 0.f) * p1.y
                           + fmaxf(fmaf(p2.x, w1.w, b1v.w), 0.f) * p2.y
                           + fmaxf(fmaf(p3.x, w1.w, b1v.w), 0.f) * p3.y;
                }
                for (; j < e; j++) {
                    float2 p = x1[csr[j]];
                    acc.x += fmaxf(fmaf(p.x, w1.x, b1v.x), 0.f) * p.y;
                    acc.y += fmaxf(fmaf(p.x, w1.y, b1v.y), 0.f) * p.y;
                    acc.z += fmaxf(fmaf(p.x, w1.z, b1v.z), 0.f) * p.y;
                    acc.w += fmaxf(fmaf(p.x, w1.w, b1v.w), 0.f) * p.y;
                }
            }
            float cdv = cdm[nl];
            store_A(smem, nl, lane, acc.x * cdv, acc.y * cdv, acc.z * cdv, acc.w * cdv);
        }
    }

    mma_gemm(smem, smem_base, 0, nbase, bb, csm, 1, g_hfA[br], nullptr, t);
}

// ---------------- layers 3/4: fp16 row gather (MLP-8) + HMMA ----------------
// lvl=0: in hfA -> out hfB (fp16, *cs), W idx 1 ; lvl=1: in hfB -> out hsO (fp32), W idx 2
__global__ void __launch_bounds__(THREADS, 4) k_layer(int lvl, const float* __restrict__ bb) {
    extern __shared__ char smem[];
    uint32_t smem_base = smem_u32(smem);
    int br = blockIdx.y;
    int t = threadIdx.x;
    int wid = t >> 5, lane = t & 31;
    int nbase = blockIdx.x * BM;

    const uint2* in2 = (const uint2*)(lvl ? g_hfB[br] : g_hfA[br]);

    float* cdm = (float*)(smem + SM_CD);
    float* csm = (float*)(smem + SM_CS);
    if (t < BM) {
        int n = nbase + t;
        cdm[t] = (n < N_NODES) ? g_cd[br][n] : 0.f;
        csm[t] = (n < N_NODES) ? g_cs[br][n] : 0.f;
    }
    __syncthreads();

    {
        const int* csr = g_csr[br];
        #pragma unroll
        for (int q = 0; q < 8; q++) {
            int nl = wid * 8 + q;
            int n  = nbase + nl;
            float4 acc = make_float4(0.f, 0.f, 0.f, 0.f);
            if (n < N_NODES) {
                int s = g_row[br][n], e = g_row[br][n + 1];
                int j = s;
                // 8 edges in flight (MLP=8)
                for (; j + 8 <= e; j += 8) {
                    int i0 = csr[j],   i1 = csr[j+1], i2 = csr[j+2], i3 = csr[j+3];
                    int i4 = csr[j+4], i5 = csr[j+5], i6 = csr[j+6], i7 = csr[j+7];
                    uint2 v0 = in2[i0 * 32 + lane];
                    uint2 v1 = in2[i1 * 32 + lane];
                    uint2 v2 = in2[i2 * 32 + lane];
                    uint2 v3 = in2[i3 * 32 + lane];
                    uint2 v4 = in2[i4 * 32 + lane];
                    uint2 v5 = in2[i5 * 32 + lane];
                    uint2 v6 = in2[i6 * 32 + lane];
                    uint2 v7 = in2[i7 * 32 + lane];
                    acc.x += ((h_lo(v0.x) + h_lo(v1.x)) + (h_lo(v2.x) + h_lo(v3.x)))
                           + ((h_lo(v4.x) + h_lo(v5.x)) + (h_lo(v6.x) + h_lo(v7.x)));
                    acc.y += ((h_hi(v0.x) + h_hi(v1.x)) + (h_hi(v2.x) + h_hi(v3.x)))
                           + ((h_hi(v4.x) + h_hi(v5.x)) + (h_hi(v6.x) + h_hi(v7.x)));
                    acc.z += ((h_lo(v0.y) + h_lo(v1.y)) + (h_lo(v2.y) + h_lo(v3.y)))
                           + ((h_lo(v4.y) + h_lo(v5.y)) + (h_lo(v6.y) + h_lo(v7.y)));
                    acc.w += ((h_hi(v0.y) + h_hi(v1.y)) + (h_hi(v2.y) + h_hi(v3.y)))
                           + ((h_hi(v4.y) + h_hi(v5.y)) + (h_hi(v6.y) + h_hi(v7.y)));
                }
                for (; j + 4 <= e; j += 4) {
                    int i0 = csr[j], i1 = csr[j+1], i2 = csr[j+2], i3 = csr[j+3];
                    uint2 v0 = in2[i0 * 32 + lane];
                    uint2 v1 = in2[i1 * 32 + lane];
                    uint2 v2 = in2[i2 * 32 + lane];
                    uint2 v3 = in2[i3 * 32 + lane];
                    acc.x += (h_lo(v0.x) + h_lo(v1.x)) + (h_lo(v2.x) + h_lo(v3.x));
                    acc.y += (h_hi(v0.x) + h_hi(v1.x)) + (h_hi(v2.x) + h_hi(v3.x));
                    acc.z += (h_lo(v0.y) + h_lo(v1.y)) + (h_lo(v2.y) + h_lo(v3.y));
                    acc.w += (h_hi(v0.y) + h_hi(v1.y)) + (h_hi(v2.y) + h_hi(v3.y));
                }
                for (; j < e; j++) {
                    uint2 v = in2[csr[j] * 32 + lane];
                    acc.x += h_lo(v.x); acc.y += h_hi(v.x);
                    acc.z += h_lo(v.y); acc.w += h_hi(v.y);
                }
            }
            float cdv = cdm[nl];
            store_A(smem, nl, lane, acc.x * cdv, acc.y * cdv, acc.z * cdv, acc.w * cdv);
        }
    }

    if (lvl == 0)
        mma_gemm(smem, smem_base, 1, nbase, bb, csm, 1, g_hfB[br], nullptr, t);
    else
        mma_gemm(smem, smem_base, 2, nbase, bb, csm, 0, nullptr, g_hsO[br], t);
}

// ---------------- pooling + head ----------------

__global__ void k_pool(const int* __restrict__ sg1, const int* __restrict__ sg2,
                       float* __restrict__ out) {
    int br = blockIdx.z;
    const int* seg = br ? sg2 : sg1;
    float* outg = out + br * N_GRAPHS * HID;
    const float* hs = g_hsO[br];
    int g = blockIdx.x, slice = blockIdx.y, j = threadIdx.x;
    int lo = 0, hi = N_NODES;
    while (lo < hi) { int m = (lo + hi) >> 1; if (seg[m] < g) lo = m + 1; else hi = m; }
    int start = lo;
    hi = N_NODES;
    while (lo < hi) { int m = (lo + hi) >> 1; if (seg[m] < g + 1) lo = m + 1; else hi = m; }
    int end = lo;
    int len = end - start;
    int s0 = start + (int)(((long long)len * slice) / NSPLIT);
    int s1 = start + (int)(((long long)len * (slice + 1)) / NSPLIT);
    float s = 0.f;
    for (int n = s0; n < s1; n++) s += hs[n * HID + j];
    if (s1 > s0) atomicAdd(&outg[g * HID + j], s);
}

__global__ void k_pooldiv(const int* __restrict__ sg1, const int* __restrict__ sg2,
                          float* __restrict__ out) {
    int br = blockIdx.y;
    const int* seg = br ? sg2 : sg1;
    float* outg = out + br * N_GRAPHS * HID;
    int g = blockIdx.x, j = threadIdx.x;
    int lo = 0, hi = N_NODES;
    while (lo < hi) { int m = (lo + hi) >> 1; if (seg[m] < g) lo = m + 1; else hi = m; }
    int start = lo;
    hi = N_NODES;
    while (lo < hi) { int m = (lo + hi) >> 1; if (seg[m] < g + 1) lo = m + 1; else hi = m; }
    float cnt = (float)(lo - start);
    outg[g * HID + j] /= fmaxf(cnt, 1.0f);
}

__global__ void k_logits(const float* __restrict__ hg, const float* __restrict__ Wc,
                         const float* __restrict__ bc, float* __restrict__ outl) {
    __shared__ float dsh[HID];
    int g = blockIdx.x, t = threadIdx.x;
    dsh[t] = fabsf(hg[g * HID + t] - hg[N_GRAPHS * HID + g * HID + t]);
    __syncthreads();
    if (t < N_CLASSES) {
        float a = bc[t];
        #pragma unroll 8
        for (int k = 0; k < HID; k++) a = fmaf(dsh[k], Wc[k * N_CLASSES + t], a);
        outl[g * N_CLASSES + t] = a;
    }
}

// ---------------- launch ----------------
extern "C" void kernel_launch(void* const* d_in, const int* in_sizes, int n_in,
                              void* d_out, int out_size) {
    const int* src1 = (const int*)d_in[0];
    const int* dst1 = (const int*)d_in[1];
    const int* seg1 = (const int*)d_in[2];
    const int* src2 = (const int*)d_in[3];
    const int* dst2 = (const int*)d_in[4];
    const int* seg2 = (const int*)d_in[5];
    const float* W1 = (const float*)d_in[6];
    const float* b1 = (const float*)d_in[7];
    const float* W2 = (const float*)d_in[8];
    const float* b2 = (const float*)d_in[9];
    const float* W3 = (const float*)d_in[10];
    const float* b3 = (const float*)d_in[11];
    const float* W4 = (const float*)d_in[12];
    const float* b4 = (const float*)d_in[13];
    const float* Wc = (const float*)d_in[14];
    const float* bc = (const float*)d_in[15];
    float* out = (float*)d_out;

    cudaFuncSetAttribute(k_layer_first, cudaFuncAttributeMaxDynamicSharedMemorySize, SMEM_TOT);
    cudaFuncSetAttribute(k_layer,       cudaFuncAttributeMaxDynamicSharedMemorySize, SMEM_TOT);

    k_zero_out<<<(2 * N_GRAPHS * HID) / 256, 256>>>(out);
    k_zero_small<<<dim3(NBLK, 2), 256>>>();
    k_prepW<<<3, 256>>>(W2, W3, W4);
    k_degree<<<dim3((N_EDGES + 255) / 256, 2), 256>>>(src1, dst1, src2, dst2);

    k_scan1<<<dim3(NBLK, 2), 256>>>();
    k_scan2<<<dim3(1, 2), 512>>>();
    k_scan3<<<dim3(NBLK, 2), 256>>>();
    k_fill<<<dim3((N_EDGES + 255) / 256, 2), 256>>>(src1, dst1, src2, dst2);
    k_x1<<<dim3(NBLK, 2), 256>>>();

    k_layer_first<<<dim3(LGRID, 2), THREADS, SMEM_TOT>>>(W1, b1, b2);
    k_layer<<<dim3(LGRID, 2), THREADS, SMEM_TOT>>>(0, b3);
    k_layer<<<dim3(LGRID, 2), THREADS, SMEM_TOT>>>(1, b4);

    k_pool<<<dim3(N_GRAPHS, NSPLIT, 2), HID>>>(seg1, seg2, out);
    k_pooldiv<<<dim3(N_GRAPHS, 2), HID>>>(seg1, seg2, out);
    k_logits<<<N_GRAPHS, HID>>>(out, Wc, bc, out + 2 * N_GRAPHS * HID);
}